// round 8
// baseline (speedup 1.0000x reference)
#include <cuda_runtime.h>
#include <cuda_bf16.h>

// YOLOv1 loss, GB300 — sparse, half-warp-per-batch, COALESCED box-region loads.
// preds: (BSZ, 7, 7, 90) fp32   gt_boxes: (BSZ, 8, 4) fp32   gt_labels: (BSZ, 8) int32
// out: scalar fp32 total loss.

#define SS      7
#define NB      2
#define NC      80
#define NGT     8
#define FEAT    90
#define CELLS   49
#define NPRED   98
#define WPB     8                // warps per block
#define TPB     (WPB * 32)
#define BPW     2                // batch elements per warp (one per half-warp)
#define MAX_BLK 512

static __device__ double       g_partials[MAX_BLK];
static __device__ unsigned int g_count = 0;

struct BT {                       // per-batch targets (one per half-warp)
    float         conf_t[NPRED];  // 0 when no object
    float         coord[NGT][4];
    int           cell[NGT];
    unsigned int  cmask[NGT][3];  // 96-bit class one-hot union
    unsigned char hit[NPRED];     // 0 = no obj, else coord idx+1
    unsigned char cellmap[CELLS]; // 0 = unused, else cell idx+1
    int           n_cell;
    // per-GT scratch
    int   gi[NGT], gj[NGT], best[NGT], lab[NGT];
    float iou[NGT], cv[NGT][4];
};

__global__ __launch_bounds__(TPB) void yolo_fused(
    const float* __restrict__ preds,
    const float* __restrict__ gt_boxes,
    const int*   __restrict__ gt_labels,
    float*       __restrict__ out,
    int Bsz)
{
    const int w    = threadIdx.x >> 5;
    const int lane = threadIdx.x & 31;
    const int half = lane >> 4;          // 0 | 1
    const int lh   = lane & 15;          // lane within half-warp
    const int bz   = (blockIdx.x * WPB + w) * BPW + half;

    __shared__ BT     bt[WPB][BPW];
    __shared__ double s_part[WPB];
    __shared__ bool   s_last;

    float acc = 0.f;
    const bool active = (bz < Bsz);
    BT& T = bt[w][half];
    const float* p = preds + (size_t)bz * (CELLS * FEAT);

    // ---- hoist GT loads (latency overlaps zeroing) ----
    float4 g4 = make_float4(0.f, 0.f, 0.f, 0.f);
    int lab = 0;
    if (active && lh < NGT) {
        g4  = __ldg(reinterpret_cast<const float4*>(gt_boxes) + (size_t)bz * NGT + lh);
        lab = __ldg(gt_labels + bz * NGT + lh);
    }

    if (active) {
        // ---- zero target maps (half-warp) ----
        for (int i = lh; i < NPRED; i += 16) { T.conf_t[i] = 0.f; T.hit[i] = 0; }
        for (int i = lh; i < CELLS; i += 16) T.cellmap[i] = 0;

        // ---- phase 1: per-GT geometry + IoU (lh 0..7) ----
        if (lh < NGT) {
            const float x1 = g4.x, y1 = g4.y, x2 = g4.z, y2 = g4.w;
            const float cx = (x1 + x2) * 0.5f, cy = (y1 + y2) * 0.5f;
            const float bw = x2 - x1, bh = y2 - y1;
            int gi = (int)(cx * (float)SS); gi = min(max(gi, 0), SS - 1);
            int gj = (int)(cy * (float)SS); gj = min(max(gj, 0), SS - 1);

            // 5 independent float2 loads cover the 10 box floats of the cell
            const float2* pc2 = reinterpret_cast<const float2*>(p + (gj * SS + gi) * FEAT);
            const float2 u0 = __ldg(pc2 + 0);   // x0 y0
            const float2 u1 = __ldg(pc2 + 1);   // w0 h0
            const float2 u2 = __ldg(pc2 + 2);   // c0 x1
            const float2 u3 = __ldg(pc2 + 3);   // y1 w1
            const float2 u4 = __ldg(pc2 + 4);   // h1 c1
            const float pb[2][4] = { { u0.x, u0.y, u1.x, u1.y },
                                     { u2.y, u3.x, u3.y, u4.x } };
            float ious[2];
            #pragma unroll
            for (int b = 0; b < 2; b++) {
                const float pcx = (pb[b][0] + (float)gi) / (float)SS;
                const float pcy = (pb[b][1] + (float)gj) / (float)SS;
                const float pw = pb[b][2] * pb[b][2], ph = pb[b][3] * pb[b][3];
                const float bx1 = pcx - pw * 0.5f, by1 = pcy - ph * 0.5f;
                const float bx2 = pcx + pw * 0.5f, by2 = pcy + ph * 0.5f;
                const float ix1 = fmaxf(bx1, x1), iy1 = fmaxf(by1, y1);
                const float ix2 = fminf(bx2, x2), iy2 = fminf(by2, y2);
                const float inter = fmaxf(ix2 - ix1, 0.f) * fmaxf(iy2 - iy1, 0.f);
                const float a1 = fmaxf(bx2 - bx1, 0.f) * fmaxf(by2 - by1, 0.f);
                const float a2 = fmaxf(x2 - x1, 0.f) * fmaxf(y2 - y1, 0.f);
                ious[b] = inter / (a1 + a2 - inter + 1e-6f);
            }
            const int best = (ious[1] > ious[0]) ? 1 : 0;   // argmax: first wins on tie
            T.gi[lh] = gi; T.gj[lh] = gj; T.best[lh] = best; T.iou[lh] = ious[best];
            T.cv[lh][0] = cx * (float)SS - (float)gi;
            T.cv[lh][1] = cy * (float)SS - (float)gj;
            T.cv[lh][2] = sqrtf(bw);
            T.cv[lh][3] = sqrtf(bh);
            T.lab[lh] = lab;
        }
    }
    __syncwarp();

    if (active) {
        // ---- phase 2: serial scan, O(1) dedup (lh==0; SIMT-parallel halves) ----
        if (lh == 0) {
            int np = 0, nc = 0;
            #pragma unroll
            for (int k = 0; k < NGT; k++) {
                const int cell = T.gj[k] * SS + T.gi[k];
                const int pr   = cell * 2 + T.best[k];
                int j;
                const unsigned char h = T.hit[pr];
                if (h) j = h - 1; else { j = np++; T.hit[pr] = (unsigned char)(j + 1); }
                T.conf_t[pr]  = T.iou[k];                 // last-write-wins
                T.coord[j][0] = T.cv[k][0]; T.coord[j][1] = T.cv[k][1];
                T.coord[j][2] = T.cv[k][2]; T.coord[j][3] = T.cv[k][3];
                int e;
                const unsigned char m = T.cellmap[cell];
                if (m) e = m - 1;
                else {
                    e = nc++; T.cellmap[cell] = (unsigned char)(e + 1); T.cell[e] = cell;
                    T.cmask[e][0] = 0u; T.cmask[e][1] = 0u; T.cmask[e][2] = 0u;
                }
                const int l = T.lab[k];
                T.cmask[e][l >> 5] |= (1u << (l & 31));
            }
            T.n_cell = nc;
        }
        __syncwarp();

        // ---- phase 3a: box regions, COALESCED linear float2 sweep ----
        // idx -> cell = idx/5, q = idx%5; float2 address = cell*45 + q
        // consecutive lanes hit consecutive 8B words (3.2 cells / 16-lane op)
        const float2* p2 = reinterpret_cast<const float2*>(p);
        for (int idx = lh; idx < CELLS * 5; idx += 16) {
            const int c = idx / 5;
            const int q = idx - c * 5;
            const float2 v = __ldg(p2 + c * 45 + q);
            #pragma unroll
            for (int s = 0; s < 2; s++) {
                const float val = s ? v.y : v.x;
                const int f  = 2 * q + s;              // 0..9
                const int b  = (f >= 5) ? 1 : 0;
                const int r  = f - 5 * b;              // 0..4
                const int pr = 2 * c + b;
                const int h  = T.hit[pr];
                if (r == 4) {
                    const float d = val - T.conf_t[pr];
                    acc += (h ? 1.0f : 0.5f) * d * d;
                } else if (h) {
                    const float d = val - T.coord[h - 1][r];
                    acc += 5.0f * d * d;
                }
            }
        }

        // ---- phase 3b: class terms, outer cell loop, coalesced row sweep ----
        const int ncl = T.n_cell;
        for (int e = 0; e < ncl; e++) {
            const float2* row = reinterpret_cast<const float2*>(p + T.cell[e] * FEAT + NB * 5);
            const unsigned int m0 = T.cmask[e][0], m1 = T.cmask[e][1], m2 = T.cmask[e][2];
            #pragma unroll
            for (int c2 = lh; c2 < NC / 2; c2 += 16) {
                const float2 v = __ldg(row + c2);
                const int c0 = 2 * c2;
                const unsigned int mw0 = (c0 < 32) ? m0 : (c0 < 64) ? m1 : m2;
                const int c1 = c0 + 1;
                const unsigned int mw1 = (c1 < 32) ? m0 : (c1 < 64) ? m1 : m2;
                const float t0 = ((mw0 >> (c0 & 31)) & 1u) ? 1.0f : 0.0f;
                const float t1 = ((mw1 >> (c1 & 31)) & 1u) ? 1.0f : 0.0f;
                const float d0 = v.x - t0, d1 = v.y - t1;
                acc += d0 * d0 + d1 * d1;
            }
        }
    }

    // ---- warp reduce (covers both halves), fixed-order block sum ----
    #pragma unroll
    for (int o = 16; o; o >>= 1) acc += __shfl_xor_sync(0xFFFFFFFFu, acc, o);
    if (lane == 0) s_part[w] = (double)acc;
    __syncthreads();
    if (threadIdx.x == 0) {
        double s = 0.0;
        #pragma unroll
        for (int i = 0; i < WPB; i++) s += s_part[i];
        g_partials[blockIdx.x] = s;
        __threadfence();
        const unsigned int old = atomicAdd(&g_count, 1u);
        s_last = (old == (unsigned int)(gridDim.x - 1));
    }
    __syncthreads();

    // ---- fused final reduction: elected last block, fixed order ----
    if (s_last) {
        __threadfence();
        const int n = gridDim.x;
        double a = 0.0;
        for (int i = threadIdx.x; i < n; i += TPB) a += g_partials[i];
        __shared__ double s_d[TPB];
        s_d[threadIdx.x] = a;
        __syncthreads();
        #pragma unroll
        for (int s = TPB / 2; s; s >>= 1) {
            if (threadIdx.x < s) s_d[threadIdx.x] += s_d[threadIdx.x + s];
            __syncthreads();
        }
        if (threadIdx.x == 0) {
            out[0] = (float)s_d[0];
            g_count = 0;                 // reset for next graph replay
        }
    }
}

extern "C" void kernel_launch(void* const* d_in, const int* in_sizes, int n_in,
                              void* d_out, int out_size)
{
    const float* preds     = (const float*)d_in[0];
    const float* gt_boxes  = (const float*)d_in[1];
    const int*   gt_labels = (const int*)d_in[2];
    float* out = (float*)d_out;

    int Bsz = in_sizes[0] / (CELLS * FEAT);
    int grid = (Bsz + WPB * BPW - 1) / (WPB * BPW);
    if (grid > MAX_BLK) grid = MAX_BLK;

    yolo_fused<<<grid, TPB>>>(preds, gt_boxes, gt_labels, out, Bsz);
}

// round 9
// speedup vs baseline: 1.4896x; 1.4896x over previous
#include <cuda_runtime.h>
#include <cuda_bf16.h>

// YOLOv1 loss, GB300 — target-free decomposition, shfl dedup, no serial scan.
// preds: (BSZ, 7, 7, 90) fp32   gt_boxes: (BSZ, 8, 4) fp32   gt_labels: (BSZ, 8) int32
// out: scalar fp32 total loss.
//
// total = Sum 0.5*conf^2 (all 98, static addresses)
//       + Sum_{distinct gt cells} (cls - onehot)^2      (masks from gt only)
//       + Sum_{owned predictors} (conf-iou)^2 - 0.5conf^2 + 5*Sum(coord-cv)^2
//         (lane-local to the owning GT lane; no extra loads)

#define SS      7
#define NB      2
#define NC      80
#define NGT     8
#define FEAT    90
#define CELLS   49
#define NPRED   98
#define WPB     8                // warps per block
#define TPB     (WPB * 32)
#define BPW     2                // batch elements per warp (one per half-warp)
#define MAX_BLK 512
#define FULL    0xFFFFFFFFu

static __device__ double       g_partials[MAX_BLK];
static __device__ unsigned int g_count = 0;

__global__ __launch_bounds__(TPB) void yolo_fused(
    const float* __restrict__ preds,
    const float* __restrict__ gt_boxes,
    const int*   __restrict__ gt_labels,
    float*       __restrict__ out,
    int Bsz)
{
    const int w    = threadIdx.x >> 5;
    const int lane = threadIdx.x & 31;
    const int half = lane >> 4;
    const int lh   = lane & 15;
    int bz = (blockIdx.x * WPB + w) * BPW + half;
    const bool active = (bz < Bsz);
    if (!active) bz = 0;                       // clamp; contribution zeroed later
    const float* p = preds + (size_t)bz * (CELLS * FEAT);

    __shared__ int          s_cell[WPB][BPW][NGT];
    __shared__ float        s_wt  [WPB][BPW][NGT];       // 1 = leader slot
    __shared__ unsigned int s_m   [WPB][BPW][NGT][3];
    __shared__ double       s_part[WPB];
    __shared__ bool         s_last;

    // ---- hop 1: gt loads, issued first ----
    float4 g4 = make_float4(0.f, 0.f, 0.f, 0.f);
    int lab = 0;
    if (lh < NGT) {
        g4  = __ldg(reinterpret_cast<const float4*>(gt_boxes) + (size_t)bz * NGT + lh);
        lab = __ldg(gt_labels + bz * NGT + lh);
    }

    // ---- static conf sweep (overlaps hop 1; addresses independent of gt) ----
    float acc = 0.f;
    #pragma unroll
    for (int c0 = 0; c0 < CELLS; c0 += 16) {
        const int c = c0 + lh;
        if (c < CELLS) {
            const float a = __ldg(p + c * FEAT + 4);
            const float b = __ldg(p + c * FEAT + 9);
            acc += 0.5f * (a * a + b * b);
        }
    }

    // ---- geometry (GT lanes; pure ALU from gt) ----
    int   cellv = -1, gi = 0, gj = 0;
    float cv0 = 0.f, cv1 = 0.f, cv2 = 0.f, cv3 = 0.f;
    float x1 = 0.f, y1 = 0.f, x2 = 0.f, y2 = 0.f;
    if (lh < NGT) {
        x1 = g4.x; y1 = g4.y; x2 = g4.z; y2 = g4.w;
        const float cx = (x1 + x2) * 0.5f, cy = (y1 + y2) * 0.5f;
        gi = (int)(cx * (float)SS); gi = min(max(gi, 0), SS - 1);
        gj = (int)(cy * (float)SS); gj = min(max(gj, 0), SS - 1);
        cellv = gj * SS + gi;
        cv0 = cx * (float)SS - (float)gi;
        cv1 = cy * (float)SS - (float)gj;
        cv2 = sqrtf(x2 - x1);
        cv3 = sqrtf(y2 - y1);
    }

    // ---- cell dedup + class-mask union via uniform shfl loop ----
    unsigned int m0 = 0u, m1 = 0u, m2 = 0u;
    int firstk = NGT;
    #pragma unroll
    for (int k = 0; k < NGT; k++) {
        const int src = (half << 4) + k;
        const int ck = __shfl_sync(FULL, cellv, src);
        const int lk = __shfl_sync(FULL, lab,   src);
        if (lh < NGT && ck == cellv) {
            if (k < firstk) firstk = k;
            if (lk < 32)      m0 |= 1u << lk;
            else if (lk < 64) m1 |= 1u << (lk - 32);
            else              m2 |= 1u << (lk - 64);
        }
    }
    if (lh < NGT) {
        s_cell[w][half][lh] = cellv;
        s_wt  [w][half][lh] = (firstk == lh) ? 1.f : 0.f;
        s_m[w][half][lh][0] = m0; s_m[w][half][lh][1] = m1; s_m[w][half][lh][2] = m2;
    }

    // ---- hop 2 (GT lanes): box region of own cell, IoU, best ----
    int prv = -2 - lane;                 // unique sentinel for non-GT lanes
    float iou = 0.f, cb = 0.f, pb0 = 0.f, pb1 = 0.f, pb2 = 0.f, pb3 = 0.f;
    if (lh < NGT) {
        const float2* pc2 = reinterpret_cast<const float2*>(p + cellv * FEAT);
        const float2 u0 = __ldg(pc2 + 0);   // x0 y0
        const float2 u1 = __ldg(pc2 + 1);   // w0 h0
        const float2 u2 = __ldg(pc2 + 2);   // c0 x1
        const float2 u3 = __ldg(pc2 + 3);   // y1 w1
        const float2 u4 = __ldg(pc2 + 4);   // h1 c1
        const float A[2][4] = { { u0.x, u0.y, u1.x, u1.y },
                                { u2.y, u3.x, u3.y, u4.x } };
        const float confs[2] = { u2.x, u4.y };
        float ious[2];
        #pragma unroll
        for (int b = 0; b < 2; b++) {
            const float pcx = (A[b][0] + (float)gi) / (float)SS;
            const float pcy = (A[b][1] + (float)gj) / (float)SS;
            const float pw = A[b][2] * A[b][2], ph = A[b][3] * A[b][3];
            const float bx1 = pcx - pw * 0.5f, by1 = pcy - ph * 0.5f;
            const float bx2 = pcx + pw * 0.5f, by2 = pcy + ph * 0.5f;
            const float ix1 = fmaxf(bx1, x1), iy1 = fmaxf(by1, y1);
            const float ix2 = fminf(bx2, x2), iy2 = fminf(by2, y2);
            const float inter = fmaxf(ix2 - ix1, 0.f) * fmaxf(iy2 - iy1, 0.f);
            const float a1 = fmaxf(bx2 - bx1, 0.f) * fmaxf(by2 - by1, 0.f);
            const float a2 = fmaxf(x2 - x1, 0.f) * fmaxf(y2 - y1, 0.f);
            ious[b] = inter / (a1 + a2 - inter + 1e-6f);
        }
        const int best = (ious[1] > ious[0]) ? 1 : 0;   // argmax: first wins on tie
        iou = ious[best];
        prv = cellv * 2 + best;
        pb0 = A[best][0]; pb1 = A[best][1]; pb2 = A[best][2]; pb3 = A[best][3];
        cb  = confs[best];
    }

    // ---- owner = last k with same pr (last-write-wins); lane-local correction ----
    int lastk = -1;
    #pragma unroll
    for (int k = 0; k < NGT; k++) {
        const int prk = __shfl_sync(FULL, prv, (half << 4) + k);
        if (lh < NGT && prk == prv) lastk = k;          // ascending k -> max
    }
    if (lh < NGT && lastk == lh) {
        const float dc = cb - iou;
        const float d0 = pb0 - cv0, d1 = pb1 - cv1, d2 = pb2 - cv2, d3 = pb3 - cv3;
        acc += dc * dc - 0.5f * cb * cb
             + 5.f * (d0 * d0 + d1 * d1 + d2 * d2 + d3 * d3);
    }
    __syncwarp();

    // ---- class sweep: 8 slots x 40 float2, branch-free, weighted by leader flag ----
    #pragma unroll
    for (int e = 0; e < NGT; e++) {
        const int   ce = s_cell[w][half][e];
        const float wt = s_wt  [w][half][e];
        const unsigned int q0 = s_m[w][half][e][0];
        const unsigned int q1 = s_m[w][half][e][1];
        const unsigned int q2 = s_m[w][half][e][2];
        const float2* row = reinterpret_cast<const float2*>(p + ce * FEAT + NB * 5);
        float part = 0.f;
        #pragma unroll
        for (int c20 = 0; c20 < NC / 2; c20 += 16) {
            const int c2 = c20 + lh;
            if (c2 < NC / 2) {
                const float2 v = __ldg(row + c2);
                const int cc = 2 * c2;
                const unsigned int w0 = (cc < 32) ? q0 : (cc < 64) ? q1 : q2;
                const int cd = cc + 1;
                const unsigned int w1 = (cd < 32) ? q0 : (cd < 64) ? q1 : q2;
                const float t0 = ((w0 >> (cc & 31)) & 1u) ? 1.f : 0.f;
                const float t1 = ((w1 >> (cd & 31)) & 1u) ? 1.f : 0.f;
                const float e0 = v.x - t0, e1 = v.y - t1;
                part += e0 * e0 + e1 * e1;
            }
        }
        acc += wt * part;
    }

    if (!active) acc = 0.f;

    // ---- warp reduce (covers both halves), fixed-order block sum ----
    #pragma unroll
    for (int o = 16; o; o >>= 1) acc += __shfl_xor_sync(FULL, acc, o);
    if (lane == 0) s_part[w] = (double)acc;
    __syncthreads();
    if (threadIdx.x == 0) {
        double s = 0.0;
        #pragma unroll
        for (int i = 0; i < WPB; i++) s += s_part[i];
        g_partials[blockIdx.x] = s;
        __threadfence();
        const unsigned int old = atomicAdd(&g_count, 1u);
        s_last = (old == (unsigned int)(gridDim.x - 1));
    }
    __syncthreads();

    // ---- fused final reduction: elected last block, fixed order ----
    if (s_last) {
        __threadfence();
        const int n = gridDim.x;
        double a = 0.0;
        for (int i = threadIdx.x; i < n; i += TPB) a += g_partials[i];
        __shared__ double s_d[TPB];
        s_d[threadIdx.x] = a;
        __syncthreads();
        #pragma unroll
        for (int s = TPB / 2; s; s >>= 1) {
            if (threadIdx.x < s) s_d[threadIdx.x] += s_d[threadIdx.x + s];
            __syncthreads();
        }
        if (threadIdx.x == 0) {
            out[0] = (float)s_d[0];
            g_count = 0;                 // reset for next graph replay
        }
    }
}

extern "C" void kernel_launch(void* const* d_in, const int* in_sizes, int n_in,
                              void* d_out, int out_size)
{
    const float* preds     = (const float*)d_in[0];
    const float* gt_boxes  = (const float*)d_in[1];
    const int*   gt_labels = (const int*)d_in[2];
    float* out = (float*)d_out;

    int Bsz = in_sizes[0] / (CELLS * FEAT);
    int grid = (Bsz + WPB * BPW - 1) / (WPB * BPW);
    if (grid > MAX_BLK) grid = MAX_BLK;

    yolo_fused<<<grid, TPB>>>(preds, gt_boxes, gt_labels, out, Bsz);
}